// round 11
// baseline (speedup 1.0000x reference)
#include <cuda_runtime.h>
#include <cuda_fp16.h>
#include <cstdint>

#define BATCH   32
#define CIN     256
#define HW      64
#define COUT    512
#define NPIX    1024
#define KTOT    4096
#define BN_EPS  1e-5f
#define NEG_SLOPE 0.2f
#define TOPK    410

#define BM 128
#define BN 128
#define BK 64
#define NCHUNK (KTOT / BK)        // 64
#define STAGE  32768              // WH 16K + XH 16K
#define O_WH 0
#define O_XH 16384
#define NSTAGE 3
#define SMEM_DYN (1024 + NSTAGE * STAGE)

#define PW   66                   // padded width/height (halo -1..64)
#define PPIX (PW * PW)
#define NTILE 1024                // 8 n x 4 m x 32 b
#define NCTA  296                 // 148 SMs x 2 CTAs

// -------------------- scratch --------------------
__device__ float    g_sub[BATCH * CIN];
__device__ float    g_mask[BATCH * COUT];
__device__ unsigned g_wmax;        // monotone max; stable across graph replays
__device__ float    g_csum[COUT];
__device__ float    g_csq[COUT];
__device__ __half   g_Wh[COUT * KTOT];                    // k = (kh*4+kw)*256 + cin
__device__ __half   g_Xt[(size_t)BATCH * PPIX * CIN];     // padded NHWC, halo stays 0
__device__ __half   g_yh[(size_t)BATCH * COUT * NPIX];    // pre-BN y, fp16

// -------------------- PTX helpers --------------------
__device__ __forceinline__ uint32_t smem_u32(const void* p) {
    uint32_t a;
    asm("{ .reg .u64 t; cvta.to.shared.u64 t, %1; cvt.u32.u64 %0, t; }" : "=r"(a) : "l"(p));
    return a;
}
#define CP16(dst, src) \
    asm volatile("cp.async.cg.shared.global [%0], [%1], 16;" :: "r"((uint32_t)(dst)), "l"(src))
#define CP_COMMIT() asm volatile("cp.async.commit_group;" ::: "memory")
#define CP_WAIT(n)  asm volatile("cp.async.wait_group %0;" :: "n"(n) : "memory")

#define LDSM4(r, addr) \
    asm volatile("ldmatrix.sync.aligned.m8n8.x4.shared.b16 {%0,%1,%2,%3}, [%4];" \
        : "=r"((r)[0]), "=r"((r)[1]), "=r"((r)[2]), "=r"((r)[3]) : "r"(addr))

__device__ __forceinline__ void mma_f16(float* d, const uint32_t* a, uint32_t b0, uint32_t b1) {
    asm volatile("mma.sync.aligned.m16n8k16.row.col.f32.f16.f16.f32 "
        "{%0,%1,%2,%3}, {%4,%5,%6,%7}, {%8,%9}, {%0,%1,%2,%3};"
        : "+f"(d[0]), "+f"(d[1]), "+f"(d[2]), "+f"(d[3])
        : "r"(a[0]), "r"(a[1]), "r"(a[2]), "r"(a[3]), "r"(b0), "r"(b1));
}

// ==================== launch 0: wmax (2048 blocks) + zero g_sub (32 blocks) ====================
__global__ void k_pre0(const float* __restrict__ w) {
    __shared__ float red[256];
    const int blk = blockIdx.x;
    if (blk < 2048) {
        float4 v = ((const float4*)w)[(size_t)blk * 256 + threadIdx.x];
        float m = fmaxf(fmaxf(fabsf(v.x), fabsf(v.y)), fmaxf(fabsf(v.z), fabsf(v.w)));
        red[threadIdx.x] = m;
        __syncthreads();
        for (int o = 128; o > 0; o >>= 1) {
            if (threadIdx.x < o) red[threadIdx.x] = fmaxf(red[threadIdx.x], red[threadIdx.x + o]);
            __syncthreads();
        }
        if (threadIdx.x == 0) atomicMax(&g_wmax, __float_as_uint(red[0]));
    } else {
        g_sub[(blk - 2048) * 256 + threadIdx.x] = 0.f;   // reset per replay
    }
}

// ==================== launch 1: wprep (512 blocks) + transpose+|x|sum (2048 blocks) ====================
__global__ void k_pre2(const float* __restrict__ w,
                       const float* __restrict__ x,
                       const float* __restrict__ pos_p,
                       const float* __restrict__ neg_p) {
    __shared__ __align__(16) char sm[34816];
    const int blk = blockIdx.x;
    const int tid = threadIdx.x;
    if (blk < 512) {
        const int co = blk;
        const float t = 0.05f * __uint_as_float(g_wmax);
        const float pv = *pos_p, nv = *neg_p;
        const __half ph = __float2half_rn(pv);
        const __half nh = __float2half_rn(nv);
        const __half z  = __float2half_rn(0.f);
        float v[16];
        const float4* wr = (const float4*)(w + (size_t)co * 4096);
#pragma unroll
        for (int q = 0; q < 4; q++) {
            float4 f = wr[tid * 4 + q];
            v[q * 4 + 0] = f.x; v[q * 4 + 1] = f.y; v[q * 4 + 2] = f.z; v[q * 4 + 3] = f.w;
        }
        __half* wout = g_Wh + (size_t)co * 4096 + tid;
#pragma unroll
        for (int s = 0; s < 16; s++) {
            const float vv = v[s];
            wout[s * 256] = (vv > t) ? ph : ((vv < -t) ? nh : z);
        }
    } else {
        const int idx = blk - 512;
        const int b = idx >> 6, ih = idx & 63;
        __half* ts  = (__half*)sm;                       // [64][260] halves
        float* ssub = (float*)(sm + 64 * 260 * 2);       // [256] floats
        if (tid < 256) ssub[tid] = 0.f;
        __syncthreads();
        const float* xrow = x + (size_t)b * CIN * HW * HW + ih * HW;
        const int wcol = tid & 63, cing = tid >> 6;
        for (int it = 0; it < 64; it++) {
            const int cin = it * 4 + cing;
            const float v = xrow[(size_t)cin * 4096 + wcol];
            ts[wcol * 260 + cin] = __float2half_rn(v);
            float a = fabsf(v);
            a += __shfl_xor_sync(0xffffffffu, a, 16);
            a += __shfl_xor_sync(0xffffffffu, a, 8);
            a += __shfl_xor_sync(0xffffffffu, a, 4);
            a += __shfl_xor_sync(0xffffffffu, a, 2);
            a += __shfl_xor_sync(0xffffffffu, a, 1);
            if ((tid & 31) == 0) atomicAdd(&ssub[cin], a);
        }
        __syncthreads();
        __half* outp = g_Xt + ((size_t)b * PPIX + (size_t)(ih + 1) * PW + 1) * 256;
        const int cin0 = (tid & 63) * 4, wq = tid >> 6;
#pragma unroll
        for (int w2 = 0; w2 < 64; w2 += 4) {
            const int ww = w2 + wq;
            uint2 vv = *(const uint2*)&ts[ww * 260 + cin0];
            *(uint2*)(outp + (size_t)ww * 256 + cin0) = vv;
        }
        atomicAdd(&g_sub[b * CIN + tid], ssub[tid] * (1.0f / 4096.0f));
    }
}

// ==================== launch 2: saliency mask + zero BN accumulators ====================
__global__ void k_salmask(const float* __restrict__ sal_w,
                          const float* __restrict__ sal_b) {
    __shared__ float subs[CIN];
    __shared__ float sal[COUT];
    __shared__ float thr;
    const int b = blockIdx.x, c = threadIdx.x;
    if (b == 0) { g_csum[c] = 0.f; g_csq[c] = 0.f; }
    if (c < CIN) subs[c] = g_sub[b * CIN + c];
    __syncthreads();
    float s = sal_b[c];
    const float* wr = sal_w + (size_t)c * CIN;
#pragma unroll 8
    for (int i = 0; i < CIN; i++) s += subs[i] * wr[i];
    s = fabsf(s);
    sal[c] = s;
    __syncthreads();
    int gt = 0, eq = 0;
    for (int j = 0; j < COUT; j++) {
        float v = sal[j];
        gt += (v > s); eq += (v == s);
    }
    if (gt < TOPK && gt + eq >= TOPK) thr = s;
    __syncthreads();
    g_mask[b * COUT + c] = (s > thr) ? s : 0.f;
}

// ==================== launch 3: persistent conv GEMM (fp16, padded loads) ====================
__global__ void __launch_bounds__(256, 2) k_conv() {
    extern __shared__ char smraw[];
    const uint32_t sb = (smem_u32(smraw) + 1023u) & ~1023u;
    const int tid = threadIdx.x;
    const int lane = tid & 31, warp = tid >> 5;
    const int wm = warp & 1, wn = warp >> 1;

    const int gc = tid & 7, r0 = tid >> 3;
    const uint32_t swsto = (uint32_t)((gc ^ (r0 & 7)) * 16);
    const char* whp = (const char*)g_Wh;

    // smem-side (tile-invariant) ldmatrix addressing
    const int lrow = lane & 15, lsel = lane >> 4;
    const uint32_t swl = (uint32_t)(lrow & 7);
    uint32_t arow[4], brow[2], colb[4];
#pragma unroll
    for (int mi = 0; mi < 4; mi++) arow[mi] = (uint32_t)((wm * 64 + mi * 16 + lrow) * 128);
#pragma unroll
    for (int nj = 0; nj < 2; nj++) brow[nj] = (uint32_t)((wn * 32 + nj * 16 + lrow) * 128);
#pragma unroll
    for (int ks = 0; ks < 4; ks++) colb[ks] = (((uint32_t)(2 * ks + lsel)) ^ swl) * 16;

    for (int t = blockIdx.x; t < NTILE; t += NCTA) {
        const int n0 = (t & 7) * BN;
        const int m0 = ((t >> 3) & 3) * BM;
        const int b  = t >> 5;

        const size_t wbyte0 = (size_t)(m0 + r0) * 8192 + (size_t)gc * 16;
        const char* xpb[4];
#pragma unroll
        for (int j = 0; j < 4; j++) {
            const int p = n0 + r0 + 32 * j;
            const int oh = p >> 5, ow = p & 31;
            xpb[j] = (const char*)g_Xt
                   + ((size_t)b * PPIX + (size_t)(2 * oh) * PW + (size_t)(2 * ow)) * 512
                   + (size_t)gc * 16;
        }

        float acc[4][4][4];
#pragma unroll
        for (int mi = 0; mi < 4; mi++)
#pragma unroll
            for (int f = 0; f < 4; f++)
#pragma unroll
                for (int q = 0; q < 4; q++) acc[mi][f][q] = 0.f;

#define LOAD_CHUNK(c, bufb) do {                                              \
    const int _s = (c) >> 2;                                                  \
    const uint32_t _xko = (uint32_t)((((_s >> 2) * PW + (_s & 3)) << 9)       \
                                     + (((c) & 3) << 7));                     \
    const size_t _wo = wbyte0 + (size_t)(c) * 128;                            \
    _Pragma("unroll")                                                         \
    for (int _j = 0; _j < 4; _j++) {                                          \
        const uint32_t _d = (bufb) + (uint32_t)((r0 + 32 * _j) * 128) + swsto;\
        CP16(_d + O_WH, whp + _wo + (size_t)_j * 262144u);                    \
        CP16(_d + O_XH, xpb[_j] + _xko);                                      \
    }                                                                         \
} while (0)

        LOAD_CHUNK(0, sb);
        CP_COMMIT();
        LOAD_CHUNK(1, sb + STAGE);
        CP_COMMIT();

        for (int c = 0; c < NCHUNK; c++) {
            const uint32_t bufb = sb + (uint32_t)((c % NSTAGE) * STAGE);
            if (c < NCHUNK - 2) CP_WAIT(1); else CP_WAIT(0);
            __syncthreads();

#pragma unroll
            for (int ks = 0; ks < 4; ks++) {
                const uint32_t col = colb[ks];
                uint32_t bh[8], am[16];
                LDSM4(bh + 0, bufb + O_XH + brow[0] + col);
                LDSM4(bh + 4, bufb + O_XH + brow[1] + col);
#pragma unroll
                for (int mi = 0; mi < 4; mi++)
                    LDSM4(am + mi * 4, bufb + O_WH + arow[mi] + col);
#pragma unroll
                for (int mi = 0; mi < 4; mi++)
#pragma unroll
                    for (int f = 0; f < 4; f++) {
                        const int base = (f >> 1) * 4 + (f & 1);
                        mma_f16(acc[mi][f], am + mi * 4, bh[base], bh[base + 2]);
                    }
            }

            if (c + 2 < NCHUNK) {
                LOAD_CHUNK(c + 2, sb + (uint32_t)(((c + 2) % NSTAGE) * STAGE));
                CP_COMMIT();
            }
        }
#undef LOAD_CHUNK

        // ---- epilogue: FBS mask, fp16 y store, fused BN partial stats ----
        const int r = lane >> 2, cc2 = (lane & 3) * 2;
#pragma unroll
        for (int mi = 0; mi < 4; mi++) {
#pragma unroll
            for (int half = 0; half < 2; half++) {
                const int m = m0 + wm * 64 + mi * 16 + half * 8 + r;
                const float mv = g_mask[b * COUT + m];
                __half* yrow = g_yh + ((size_t)(b * COUT + m)) * NPIX + n0 + wn * 32 + cc2;
                float s1 = 0.f, s2 = 0.f;
#pragma unroll
                for (int f = 0; f < 4; f++) {
                    const float ox = acc[mi][f][half * 2 + 0] * mv;
                    const float oy = acc[mi][f][half * 2 + 1] * mv;
                    s1 += ox + oy;
                    s2 += ox * ox + oy * oy;
                    *(__half2*)(yrow + f * 8) = __floats2half2_rn(ox, oy);
                }
                s1 += __shfl_xor_sync(0xffffffffu, s1, 1);
                s2 += __shfl_xor_sync(0xffffffffu, s2, 1);
                s1 += __shfl_xor_sync(0xffffffffu, s1, 2);
                s2 += __shfl_xor_sync(0xffffffffu, s2, 2);
                if ((lane & 3) == 0) {
                    atomicAdd(&g_csum[m], s1);
                    atomicAdd(&g_csq[m],  s2);
                }
            }
        }
        __syncthreads();   // protect stage buffers before next tile's prologue
    }
}

// ==================== launch 4: BN finalize + apply + LeakyReLU ====================
__global__ void k_final(const float* __restrict__ gamma,
                        const float* __restrict__ beta,
                        float* __restrict__ out) {
    const int c = blockIdx.x & (COUT - 1);     // each block = one (b,c) channel row
    const float inv = 1.0f / (float)(BATCH * NPIX);
    const float mean = g_csum[c] * inv;
    const float var  = g_csq[c] * inv - mean * mean;
    const float rstd = rsqrtf(var + BN_EPS);
    const float scale = rstd * gamma[c];
    const float shift = beta[c] - mean * scale;
    const size_t i = (size_t)blockIdx.x * 256 + threadIdx.x;
    const uint2 raw = ((const uint2*)g_yh)[i];
    const float2 v01 = __half22float2(*(const __half2*)&raw.x);
    const float2 v23 = __half22float2(*(const __half2*)&raw.y);
    float4 o; float t;
    t = v01.x * scale + shift; o.x = (t > 0.f) ? t : NEG_SLOPE * t;
    t = v01.y * scale + shift; o.y = (t > 0.f) ? t : NEG_SLOPE * t;
    t = v23.x * scale + shift; o.z = (t > 0.f) ? t : NEG_SLOPE * t;
    t = v23.y * scale + shift; o.w = (t > 0.f) ? t : NEG_SLOPE * t;
    ((float4*)out)[i] = o;
}

// -------------------- launcher --------------------
extern "C" void kernel_launch(void* const* d_in, const int* in_sizes, int n_in,
                              void* d_out, int out_size) {
    const float* x      = (const float*)d_in[0];
    const float* weight = (const float*)d_in[1];
    const float* pos    = (const float*)d_in[2];
    const float* neg    = (const float*)d_in[3];
    const float* sal_w  = (const float*)d_in[4];
    const float* sal_b  = (const float*)d_in[5];
    const float* gamma  = (const float*)d_in[6];
    const float* beta   = (const float*)d_in[7];
    float* out = (float*)d_out;

    cudaFuncSetAttribute(k_conv, cudaFuncAttributeMaxDynamicSharedMemorySize, SMEM_DYN);

    k_pre0<<<2080, 256>>>(weight);                                   // 0: wmax + zero sub
    k_pre2<<<2560, 256>>>(weight, x, pos, neg);                      // 1: wprep + transpose
    k_salmask<<<BATCH, 512>>>(sal_w, sal_b);                         // 2: mask + zero stats
    k_conv<<<NCTA, 256, SMEM_DYN>>>();                               // 3: persistent conv
    k_final<<<(BATCH * COUT * NPIX) / 4 / 256, 256>>>(gamma, beta, out);  // 4
}

// round 12
// speedup vs baseline: 1.0486x; 1.0486x over previous
#include <cuda_runtime.h>
#include <cuda_fp16.h>
#include <cstdint>

#define BATCH   32
#define CIN     256
#define HW      64
#define COUT    512
#define NPIX    1024
#define KTOT    4096
#define BN_EPS  1e-5f
#define NEG_SLOPE 0.2f
#define TOPK    410

#define BM 128
#define BN 128
#define BK 64
#define NCHUNK (KTOT / BK)        // 64
#define STAGE  32768              // WH 16K + XH 16K
#define O_WH 0
#define O_XH 16384
#define NSTAGE 3
#define SMEM_DYN (1024 + NSTAGE * STAGE)

#define PW   66                   // padded width/height (halo -1..64)
#define PPIX (PW * PW)

// -------------------- scratch --------------------
__device__ float    g_sub[BATCH * CIN];
__device__ float    g_mask[BATCH * COUT];
__device__ unsigned g_wmax;        // monotone max; stable across graph replays
__device__ float    g_csum[COUT];
__device__ float    g_csq[COUT];
__device__ __half   g_Wh[COUT * KTOT];                    // k = (kh*4+kw)*256 + cin
__device__ __half   g_Xt[(size_t)BATCH * PPIX * CIN];     // padded NHWC, halo stays 0
__device__ __half   g_yh[(size_t)BATCH * COUT * NPIX];    // pre-BN y, fp16

// -------------------- PTX helpers --------------------
__device__ __forceinline__ uint32_t smem_u32(const void* p) {
    uint32_t a;
    asm("{ .reg .u64 t; cvta.to.shared.u64 t, %1; cvt.u32.u64 %0, t; }" : "=r"(a) : "l"(p));
    return a;
}
#define CP16(dst, src) \
    asm volatile("cp.async.cg.shared.global [%0], [%1], 16;" :: "r"((uint32_t)(dst)), "l"(src))
#define CP_COMMIT() asm volatile("cp.async.commit_group;" ::: "memory")
#define CP_WAIT(n)  asm volatile("cp.async.wait_group %0;" :: "n"(n) : "memory")

#define LDSM4(r, addr) \
    asm volatile("ldmatrix.sync.aligned.m8n8.x4.shared.b16 {%0,%1,%2,%3}, [%4];" \
        : "=r"((r)[0]), "=r"((r)[1]), "=r"((r)[2]), "=r"((r)[3]) : "r"(addr))

__device__ __forceinline__ void mma_f16(float* d, const uint32_t* a, uint32_t b0, uint32_t b1) {
    asm volatile("mma.sync.aligned.m16n8k16.row.col.f32.f16.f16.f32 "
        "{%0,%1,%2,%3}, {%4,%5,%6,%7}, {%8,%9}, {%0,%1,%2,%3};"
        : "+f"(d[0]), "+f"(d[1]), "+f"(d[2]), "+f"(d[3])
        : "r"(a[0]), "r"(a[1]), "r"(a[2]), "r"(a[3]), "r"(b0), "r"(b1));
}

// ==================== launch 0: wmax (2048 blocks) + zero g_sub (32 blocks) ====================
__global__ void k_pre0(const float* __restrict__ w) {
    __shared__ float red[256];
    const int blk = blockIdx.x;
    if (blk < 2048) {
        float4 v = ((const float4*)w)[(size_t)blk * 256 + threadIdx.x];
        float m = fmaxf(fmaxf(fabsf(v.x), fabsf(v.y)), fmaxf(fabsf(v.z), fabsf(v.w)));
        red[threadIdx.x] = m;
        __syncthreads();
        for (int o = 128; o > 0; o >>= 1) {
            if (threadIdx.x < o) red[threadIdx.x] = fmaxf(red[threadIdx.x], red[threadIdx.x + o]);
            __syncthreads();
        }
        if (threadIdx.x == 0) atomicMax(&g_wmax, __float_as_uint(red[0]));
    } else {
        g_sub[(blk - 2048) * 256 + threadIdx.x] = 0.f;   // reset per replay
    }
}

// ==================== launch 1: wprep (512 blocks) + transpose+|x|sum (2048 blocks) ====================
__global__ void k_pre2(const float* __restrict__ w,
                       const float* __restrict__ x,
                       const float* __restrict__ pos_p,
                       const float* __restrict__ neg_p) {
    __shared__ __align__(16) char sm[33280];
    const int blk = blockIdx.x;
    const int tid = threadIdx.x;
    if (blk < 512) {
        const int co = blk;
        const float t = 0.05f * __uint_as_float(g_wmax);
        const float pv = *pos_p, nv = *neg_p;
        const __half ph = __float2half_rn(pv);
        const __half nh = __float2half_rn(nv);
        const __half z  = __float2half_rn(0.f);
        float v[16];
        const float4* wr = (const float4*)(w + (size_t)co * 4096);
#pragma unroll
        for (int q = 0; q < 4; q++) {
            float4 f = wr[tid * 4 + q];
            v[q * 4 + 0] = f.x; v[q * 4 + 1] = f.y; v[q * 4 + 2] = f.z; v[q * 4 + 3] = f.w;
        }
        __half* wout = g_Wh + (size_t)co * 4096 + tid;
#pragma unroll
        for (int s = 0; s < 16; s++) {
            const float vv = v[s];
            wout[s * 256] = (vv > t) ? ph : ((vv < -t) ? nh : z);
        }
    } else {
        // ---- transpose x[b][cin][ih][:] -> padded Xt[b][ih+1][iw+1][cin] ----
        const int idx = blk - 512;
        const int b = idx >> 6, ih = idx & 63;
        __half* ts = (__half*)sm;                        // [64][260] halves
        const float* xrow = x + (size_t)b * CIN * HW * HW + ih * HW;
        const int wcol = tid & 63, cing = tid >> 6;
#pragma unroll 8
        for (int it = 0; it < 64; it++) {
            const int cin = it * 4 + cing;
            ts[wcol * 260 + cin] = __float2half_rn(xrow[(size_t)cin * 4096 + wcol]);
        }
        __syncthreads();
        // write out (coalesced along cin)
        __half* outp = g_Xt + ((size_t)b * PPIX + (size_t)(ih + 1) * PW + 1) * 256;
        const int cin0 = (tid & 63) * 4, wq = tid >> 6;
#pragma unroll
        for (int w2 = 0; w2 < 64; w2 += 4) {
            const int ww = w2 + wq;
            uint2 vv = *(const uint2*)&ts[ww * 260 + cin0];
            *(uint2*)(outp + (size_t)ww * 256 + cin0) = vv;
        }
        // |x| row-sum from resident smem tile: thread tid owns cin=tid
        float s = 0.f;
#pragma unroll 8
        for (int ww = 0; ww < 64; ww++)
            s += fabsf(__half2float(ts[ww * 260 + tid]));
        atomicAdd(&g_sub[b * CIN + tid], s * (1.0f / 4096.0f));
    }
}

// ==================== launch 2: saliency mask + zero BN accumulators ====================
__global__ void k_salmask(const float* __restrict__ sal_w,
                          const float* __restrict__ sal_b) {
    __shared__ float subs[CIN];
    __shared__ float sal[COUT];
    __shared__ float thr;
    const int b = blockIdx.x, c = threadIdx.x;
    if (b == 0) { g_csum[c] = 0.f; g_csq[c] = 0.f; }
    if (c < CIN) subs[c] = g_sub[b * CIN + c];
    __syncthreads();
    float s = sal_b[c];
    const float* wr = sal_w + (size_t)c * CIN;
#pragma unroll 8
    for (int i = 0; i < CIN; i++) s += subs[i] * wr[i];
    s = fabsf(s);
    sal[c] = s;
    __syncthreads();
    int gt = 0, eq = 0;
    for (int j = 0; j < COUT; j++) {
        float v = sal[j];
        gt += (v > s); eq += (v == s);
    }
    if (gt < TOPK && gt + eq >= TOPK) thr = s;
    __syncthreads();
    g_mask[b * COUT + c] = (s > thr) ? s : 0.f;
}

// ==================== launch 3: conv GEMM (fp16, branch-free padded loads) ====================
__global__ void __launch_bounds__(256, 2) k_conv() {
    extern __shared__ char smraw[];
    const uint32_t sb = (smem_u32(smraw) + 1023u) & ~1023u;
    const int tid = threadIdx.x;
    const int lane = tid & 31, warp = tid >> 5;
    const int wm = warp & 1, wn = warp >> 1;
    const int b = blockIdx.z, m0 = blockIdx.y * BM, n0 = blockIdx.x * BN;

    const int gc = tid & 7, r0 = tid >> 3;
    const uint32_t swsto = (uint32_t)((gc ^ (r0 & 7)) * 16);
    const char* whp = (const char*)g_Wh;
    const size_t wbyte0 = (size_t)(m0 + r0) * 8192 + (size_t)gc * 16;
    const char* xpb[4];
#pragma unroll
    for (int j = 0; j < 4; j++) {
        const int p = n0 + r0 + 32 * j;
        const int oh = p >> 5, ow = p & 31;
        xpb[j] = (const char*)g_Xt + ((size_t)b * PPIX + (size_t)(2 * oh) * PW + (size_t)(2 * ow)) * 512
               + (size_t)gc * 16;
    }

    const int lrow = lane & 15, lsel = lane >> 4;
    const uint32_t swl = (uint32_t)(lrow & 7);
    uint32_t arow[4], brow[2], colb[4];
#pragma unroll
    for (int mi = 0; mi < 4; mi++) arow[mi] = (uint32_t)((wm * 64 + mi * 16 + lrow) * 128);
#pragma unroll
    for (int nj = 0; nj < 2; nj++) brow[nj] = (uint32_t)((wn * 32 + nj * 16 + lrow) * 128);
#pragma unroll
    for (int ks = 0; ks < 4; ks++) colb[ks] = (((uint32_t)(2 * ks + lsel)) ^ swl) * 16;

    float acc[4][4][4];
#pragma unroll
    for (int mi = 0; mi < 4; mi++)
#pragma unroll
        for (int f = 0; f < 4; f++)
#pragma unroll
            for (int q = 0; q < 4; q++) acc[mi][f][q] = 0.f;

#define LOAD_CHUNK(c, bufb) do {                                              \
    const int _s = (c) >> 2;                                                  \
    const uint32_t _xko = (uint32_t)((((_s >> 2) * PW + (_s & 3)) << 9)       \
                                     + (((c) & 3) << 7));                     \
    const size_t _wo = wbyte0 + (size_t)(c) * 128;                            \
    _Pragma("unroll")                                                         \
    for (int _j = 0; _j < 4; _j++) {                                          \
        const uint32_t _d = (bufb) + (uint32_t)((r0 + 32 * _j) * 128) + swsto;\
        CP16(_d + O_WH, whp + _wo + (size_t)_j * 262144u);                    \
        CP16(_d + O_XH, xpb[_j] + _xko);                                      \
    }                                                                         \
} while (0)

    LOAD_CHUNK(0, sb);
    CP_COMMIT();
    LOAD_CHUNK(1, sb + STAGE);
    CP_COMMIT();

    for (int c = 0; c < NCHUNK; c++) {
        const uint32_t bufb = sb + (uint32_t)((c % NSTAGE) * STAGE);
        CP_WAIT(1);
        __syncthreads();

#pragma unroll
        for (int ks = 0; ks < 4; ks++) {
            const uint32_t col = colb[ks];
            uint32_t bh[8], am[16];
            LDSM4(bh + 0, bufb + O_XH + brow[0] + col);
            LDSM4(bh + 4, bufb + O_XH + brow[1] + col);
#pragma unroll
            for (int mi = 0; mi < 4; mi++)
                LDSM4(am + mi * 4, bufb + O_WH + arow[mi] + col);
#pragma unroll
            for (int mi = 0; mi < 4; mi++)
#pragma unroll
                for (int f = 0; f < 4; f++) {
                    const int base = (f >> 1) * 4 + (f & 1);
                    mma_f16(acc[mi][f], am + mi * 4, bh[base], bh[base + 2]);
                }
        }

        if (c + 2 < NCHUNK)
            LOAD_CHUNK(c + 2, sb + (uint32_t)(((c + 2) % NSTAGE) * STAGE));
        CP_COMMIT();
    }
#undef LOAD_CHUNK

    // ---- epilogue: FBS mask, fp16 y store, fused BN partial stats ----
    const int r = lane >> 2, cc2 = (lane & 3) * 2;
#pragma unroll
    for (int mi = 0; mi < 4; mi++) {
#pragma unroll
        for (int half = 0; half < 2; half++) {
            const int m = m0 + wm * 64 + mi * 16 + half * 8 + r;
            const float mv = g_mask[b * COUT + m];
            __half* yrow = g_yh + ((size_t)(b * COUT + m)) * NPIX + n0 + wn * 32 + cc2;
            float s1 = 0.f, s2 = 0.f;
#pragma unroll
            for (int f = 0; f < 4; f++) {
                const float ox = acc[mi][f][half * 2 + 0] * mv;
                const float oy = acc[mi][f][half * 2 + 1] * mv;
                s1 += ox + oy;
                s2 += ox * ox + oy * oy;
                *(__half2*)(yrow + f * 8) = __floats2half2_rn(ox, oy);
            }
            s1 += __shfl_xor_sync(0xffffffffu, s1, 1);
            s2 += __shfl_xor_sync(0xffffffffu, s2, 1);
            s1 += __shfl_xor_sync(0xffffffffu, s1, 2);
            s2 += __shfl_xor_sync(0xffffffffu, s2, 2);
            if ((lane & 3) == 0) {
                atomicAdd(&g_csum[m], s1);
                atomicAdd(&g_csq[m],  s2);
            }
        }
    }
}

// ==================== launch 4: BN finalize + apply + LeakyReLU ====================
__global__ void k_final(const float* __restrict__ gamma,
                        const float* __restrict__ beta,
                        float* __restrict__ out) {
    const int c = blockIdx.x & (COUT - 1);     // each block = one (b,c) channel row
    const float inv = 1.0f / (float)(BATCH * NPIX);
    const float mean = g_csum[c] * inv;
    const float var  = g_csq[c] * inv - mean * mean;
    const float rstd = rsqrtf(var + BN_EPS);
    const float scale = rstd * gamma[c];
    const float shift = beta[c] - mean * scale;
    const size_t i = (size_t)blockIdx.x * 256 + threadIdx.x;
    const uint2 raw = ((const uint2*)g_yh)[i];
    const float2 v01 = __half22float2(*(const __half2*)&raw.x);
    const float2 v23 = __half22float2(*(const __half2*)&raw.y);
    float4 o; float t;
    t = v01.x * scale + shift; o.x = (t > 0.f) ? t : NEG_SLOPE * t;
    t = v01.y * scale + shift; o.y = (t > 0.f) ? t : NEG_SLOPE * t;
    t = v23.x * scale + shift; o.z = (t > 0.f) ? t : NEG_SLOPE * t;
    t = v23.y * scale + shift; o.w = (t > 0.f) ? t : NEG_SLOPE * t;
    ((float4*)out)[i] = o;
}

// -------------------- launcher --------------------
extern "C" void kernel_launch(void* const* d_in, const int* in_sizes, int n_in,
                              void* d_out, int out_size) {
    const float* x      = (const float*)d_in[0];
    const float* weight = (const float*)d_in[1];
    const float* pos    = (const float*)d_in[2];
    const float* neg    = (const float*)d_in[3];
    const float* sal_w  = (const float*)d_in[4];
    const float* sal_b  = (const float*)d_in[5];
    const float* gamma  = (const float*)d_in[6];
    const float* beta   = (const float*)d_in[7];
    float* out = (float*)d_out;

    cudaFuncSetAttribute(k_conv, cudaFuncAttributeMaxDynamicSharedMemorySize, SMEM_DYN);

    k_pre0<<<2080, 256>>>(weight);                                   // 0: wmax + zero sub
    k_pre2<<<2560, 256>>>(weight, x, pos, neg);                      // 1: wprep + transpose
    k_salmask<<<BATCH, 512>>>(sal_w, sal_b);                         // 2: mask + zero stats
    dim3 cg(NPIX / BN, COUT / BM, BATCH);                            // (8, 4, 32)
    k_conv<<<cg, 256, SMEM_DYN>>>();                                 // 3: conv (profiled)
    k_final<<<(BATCH * COUT * NPIX) / 4 / 256, 256>>>(gamma, beta, out);  // 4
}